// round 3
// baseline (speedup 1.0000x reference)
#include <cuda_runtime.h>
#include <cuda_bf16.h>

#define SEQ     2048
#define DIM     256
#define NHEAD   8
#define HD      32
#define NBATCH  4
#define QK_SCALE 0.17677669529663687f   // 32^-0.5

// Scratch: Q (pre-scaled), K, V in [B, H, N, 32] layout (8 MB each)
__device__ float g_q[NBATCH * NHEAD * SEQ * HD];
__device__ float g_k[NBATCH * NHEAD * SEQ * HD];
__device__ float g_v[NBATCH * NHEAD * SEQ * HD];

// ---------------------------------------------------------------------------
// Kernel 1: fused QKV projection.  y[m, n3] = x[m, :256] @ W[:, n3] + b[n3]
// M = 8192, N = 768, K = 256.  64x64 block tile, 256 threads, 4x4 micro-tile.
// Scatter into g_q/g_k/g_v ([B,H,N,32]); Q gets QK_SCALE folded in.
// ---------------------------------------------------------------------------
__global__ __launch_bounds__(256) void qkv_gemm(const float* __restrict__ x,
                                                const float* __restrict__ W,
                                                const float* __restrict__ bias) {
    __shared__ float As[32][65];   // [k][m], padded: conflict-free transpose store
    __shared__ float Bs[32][64];   // [k][n]

    const int tid = threadIdx.x;
    const int m0 = blockIdx.x * 64;
    const int n0 = blockIdx.y * 64;
    const int tx = tid & 15;       // micro-tile col group
    const int ty = tid >> 4;       // micro-tile row group

    const int xr = tid >> 3;             // 0..31
    const int xk = (tid & 7) << 2;       // 0,4,...,28
    const int wr = tid >> 4;             // 0..15
    const int wc = (tid & 15) << 2;      // 0,4,...,60

    float c[4][4] = {};

    for (int k0 = 0; k0 < 256; k0 += 32) {
        #pragma unroll
        for (int rr = 0; rr < 64; rr += 32) {
            float4 v = *reinterpret_cast<const float4*>(
                &x[(size_t)(m0 + xr + rr) * 256 + k0 + xk]);
            As[xk + 0][xr + rr] = v.x;
            As[xk + 1][xr + rr] = v.y;
            As[xk + 2][xr + rr] = v.z;
            As[xk + 3][xr + rr] = v.w;
        }
        #pragma unroll
        for (int rr = 0; rr < 32; rr += 16) {
            *reinterpret_cast<float4*>(&Bs[wr + rr][wc]) =
                *reinterpret_cast<const float4*>(
                    &W[(size_t)(k0 + wr + rr) * 768 + n0 + wc]);
        }
        __syncthreads();

        #pragma unroll
        for (int kk = 0; kk < 32; kk++) {
            float a[4], b[4];
            float4 bv = *reinterpret_cast<const float4*>(&Bs[kk][tx << 2]);
            b[0] = bv.x; b[1] = bv.y; b[2] = bv.z; b[3] = bv.w;
            #pragma unroll
            for (int i = 0; i < 4; i++) a[i] = As[kk][(ty << 2) + i];
            #pragma unroll
            for (int i = 0; i < 4; i++)
                #pragma unroll
                for (int j = 0; j < 4; j++) c[i][j] += a[i] * b[j];
        }
        __syncthreads();
    }

    #pragma unroll
    for (int i = 0; i < 4; i++) {
        const int m  = m0 + (ty << 2) + i;
        const int bb = m >> 11;          // batch
        const int n  = m & 2047;         // seq position
        #pragma unroll
        for (int j = 0; j < 4; j++) {
            const int n3 = n0 + (tx << 2) + j;
            float val = c[i][j] + bias[n3];
            const int which = n3 >> 8;   // 0=Q 1=K 2=V
            const int cc = n3 & 255;
            const int h = cc >> 5, d = cc & 31;
            const size_t idx = ((size_t)(bb * NHEAD + h) * SEQ + n) * HD + d;
            if (which == 0)      g_q[idx] = val * QK_SCALE;
            else if (which == 1) g_k[idx] = val;
            else                 g_v[idx] = val;
        }
    }
}

// ---------------------------------------------------------------------------
// Kernel 2: flash attention with block mask.
// Mask: rows < 1024 see cols [0,1024); rows >= 1024 are causal (col <= row).
// MASK_NEG = -1000 makes masked probs exactly 0 in fp32, so masked k-tiles are
// skipped entirely (bit-identical to reference softmax).
// Grid: (q_tile 0..31, b*h 0..31).  256 threads.  64-row q-tile, 64-col k-tile.
// ---------------------------------------------------------------------------
__global__ __launch_bounds__(256) void flash_attn(float* __restrict__ out) {
    const int qt = blockIdx.x;          // q tile
    const int bh = blockIdx.y;          // b*8 + h
    const int b = bh >> 3, h = bh & 7;

    const float* Q = g_q + (size_t)bh * SEQ * HD;
    const float* K = g_k + (size_t)bh * SEQ * HD;
    const float* V = g_v + (size_t)bh * SEQ * HD;

    __shared__ float Qs[32][65];        // [d][row], padded
    __shared__ float Ks[32][65];        // [d][col], padded
    __shared__ float Vs[64][36];        // [pos][d], padded (float4-aligned)
    __shared__ float Ss[64][65];        // scores / probs
    __shared__ float m_s[64], l_s[64], f_s[64];

    const int tid = threadIdx.x;
    const int tx = tid & 15, ty = tid >> 4;
    const int lr = tid >> 3;            // 0..31
    const int ld = (tid & 7) << 2;      // 0..28

    // Load Q tile transposed
    #pragma unroll
    for (int rr = 0; rr < 64; rr += 32) {
        float4 v = *reinterpret_cast<const float4*>(
            &Q[(size_t)(qt * 64 + lr + rr) * HD + ld]);
        Qs[ld + 0][lr + rr] = v.x;
        Qs[ld + 1][lr + rr] = v.y;
        Qs[ld + 2][lr + rr] = v.z;
        Qs[ld + 3][lr + rr] = v.w;
    }
    if (tid < 64) { m_s[tid] = -3.0e38f; l_s[tid] = 0.f; }

    float acc[4][2] = {};
    const bool bottom = (qt >= 16);
    const int nkt = bottom ? (qt + 1) : 16;

    for (int kt = 0; kt < nkt; kt++) {
        __syncthreads();   // prev iteration done with Ks/Vs/Ss
        #pragma unroll
        for (int rr = 0; rr < 64; rr += 32) {
            float4 v = *reinterpret_cast<const float4*>(
                &K[(size_t)(kt * 64 + lr + rr) * HD + ld]);
            Ks[ld + 0][lr + rr] = v.x;
            Ks[ld + 1][lr + rr] = v.y;
            Ks[ld + 2][lr + rr] = v.z;
            Ks[ld + 3][lr + rr] = v.w;
            float4 w = *reinterpret_cast<const float4*>(
                &V[(size_t)(kt * 64 + lr + rr) * HD + ld]);
            *reinterpret_cast<float4*>(&Vs[lr + rr][ld]) = w;
        }
        __syncthreads();

        // S = Q K^T  (Q pre-scaled): 4x4 micro-tile per thread
        float cs[4][4] = {};
        #pragma unroll
        for (int kk = 0; kk < 32; kk++) {
            float a[4], bk[4];
            #pragma unroll
            for (int i = 0; i < 4; i++) a[i]  = Qs[kk][(ty << 2) + i];
            #pragma unroll
            for (int j = 0; j < 4; j++) bk[j] = Ks[kk][(tx << 2) + j];
            #pragma unroll
            for (int i = 0; i < 4; i++)
                #pragma unroll
                for (int j = 0; j < 4; j++) cs[i][j] += a[i] * bk[j];
        }
        // Only the diagonal tile of the causal half needs masking
        if (bottom && kt == qt) {
            #pragma unroll
            for (int i = 0; i < 4; i++) {
                const int gr = qt * 64 + (ty << 2) + i;
                #pragma unroll
                for (int j = 0; j < 4; j++) {
                    const int gc = kt * 64 + (tx << 2) + j;
                    if (gc > gr) cs[i][j] = -3.0e38f;
                }
            }
        }
        #pragma unroll
        for (int i = 0; i < 4; i++)
            #pragma unroll
            for (int j = 0; j < 4; j++)
                Ss[(ty << 2) + i][(tx << 2) + j] = cs[i][j];
        __syncthreads();

        // Online softmax: 4 threads per row, 16 cols each
        {
            const int r = tid >> 2;
            const int base = (tid & 3) << 4;
            float mx = -3.0e38f;
            #pragma unroll
            for (int cix = 0; cix < 16; cix++) mx = fmaxf(mx, Ss[r][base + cix]);
            mx = fmaxf(mx, __shfl_xor_sync(0xffffffffu, mx, 1));
            mx = fmaxf(mx, __shfl_xor_sync(0xffffffffu, mx, 2));
            const float mo = m_s[r];
            const float mn = fmaxf(mo, mx);
            float sum = 0.f;
            #pragma unroll
            for (int cix = 0; cix < 16; cix++) {
                float p = __expf(Ss[r][base + cix] - mn);
                Ss[r][base + cix] = p;
                sum += p;
            }
            // shfl barriers also order the m_s read (above) before the write (below)
            sum += __shfl_xor_sync(0xffffffffu, sum, 1);
            sum += __shfl_xor_sync(0xffffffffu, sum, 2);
            if ((tid & 3) == 0) {
                const float f = __expf(mo - mn);
                f_s[r] = f;
                l_s[r] = l_s[r] * f + sum;
                m_s[r] = mn;
            }
        }
        __syncthreads();

        // O = O*f + P @ V : thread owns 4 rows x 2 output dims
        float fr[4];
        #pragma unroll
        for (int i = 0; i < 4; i++) fr[i] = f_s[(ty << 2) + i];
        #pragma unroll
        for (int i = 0; i < 4; i++) { acc[i][0] *= fr[i]; acc[i][1] *= fr[i]; }
        #pragma unroll
        for (int kk = 0; kk < 64; kk++) {
            float2 vv = *reinterpret_cast<const float2*>(&Vs[kk][tx << 1]);
            #pragma unroll
            for (int i = 0; i < 4; i++) {
                const float p = Ss[(ty << 2) + i][kk];
                acc[i][0] += p * vv.x;
                acc[i][1] += p * vv.y;
            }
        }
    }
    __syncthreads();

    #pragma unroll
    for (int i = 0; i < 4; i++) {
        const int r = (ty << 2) + i;
        const float inv = 1.f / l_s[r];
        float2 o;
        o.x = acc[i][0] * inv;
        o.y = acc[i][1] * inv;
        const size_t oidx =
            ((size_t)(b * SEQ + qt * 64 + r)) * DIM + h * HD + (tx << 1);
        *reinterpret_cast<float2*>(&out[oidx]) = o;
    }
}

extern "C" void kernel_launch(void* const* d_in, const int* in_sizes, int n_in,
                              void* d_out, int out_size) {
    const float* x    = (const float*)d_in[0];   // [4, 2048, 256]
    const float* W    = (const float*)d_in[1];   // [256, 768]
    const float* bias = (const float*)d_in[2];   // [768]
    float* out = (float*)d_out;                  // [4, 2048, 256]

    dim3 gemm_grid(8192 / 64, 768 / 64);         // 128 x 12
    qkv_gemm<<<gemm_grid, 256>>>(x, W, bias);

    dim3 attn_grid(32, 32);                      // (q_tile, b*h)
    flash_attn<<<attn_grid, 256>>>(out);
}

// round 5
// speedup vs baseline: 2.4210x; 2.4210x over previous
#include <cuda_runtime.h>
#include <cuda_bf16.h>
#include <cstdint>

#define SEQ     2048
#define DIM     256
#define NHEAD   8
#define HD      32
#define NBATCH  4
#define NBH     (NBATCH * NHEAD)
#define QK_SCALE 0.17677669529663687f   // 32^-0.5

// bf16 hi/lo split scratch
__device__ __align__(16) __nv_bfloat16 g_qh[NBH * SEQ * HD];
__device__ __align__(16) __nv_bfloat16 g_ql[NBH * SEQ * HD];
__device__ __align__(16) __nv_bfloat16 g_kh[NBH * SEQ * HD];
__device__ __align__(16) __nv_bfloat16 g_kl[NBH * SEQ * HD];
__device__ __align__(16) float         g_v [NBH * SEQ * HD];   // fp32, [bh][n][d]
__device__ __align__(16) __nv_bfloat16 g_vth[NBH * HD * SEQ];  // V^T hi, [bh][d][n]
__device__ __align__(16) __nv_bfloat16 g_vtl[NBH * HD * SEQ];  // V^T lo

// ---------------------------------------------------------------------------
// helpers
// ---------------------------------------------------------------------------
// pack two f32 -> bf16x2 (low half = x0), plus bf16 residues packed likewise
__device__ __forceinline__ void split_pack(float x0, float x1,
                                           uint32_t& h, uint32_t& l) {
    uint32_t hp;
    asm("cvt.rn.bf16x2.f32 %0, %1, %2;" : "=r"(hp) : "f"(x1), "f"(x0));
    float h0 = __uint_as_float(hp << 16);
    float h1 = __uint_as_float(hp & 0xFFFF0000u);
    h = hp;
    asm("cvt.rn.bf16x2.f32 %0, %1, %2;" : "=r"(l) : "f"(x1 - h1), "f"(x0 - h0));
}

__device__ __forceinline__ void mma16816(float* c, const uint32_t* a,
                                         uint32_t b0, uint32_t b1) {
    asm volatile(
        "mma.sync.aligned.m16n8k16.row.col.f32.bf16.bf16.f32 "
        "{%0,%1,%2,%3}, {%4,%5,%6,%7}, {%8,%9}, {%0,%1,%2,%3};"
        : "+f"(c[0]), "+f"(c[1]), "+f"(c[2]), "+f"(c[3])
        : "r"(a[0]), "r"(a[1]), "r"(a[2]), "r"(a[3]), "r"(b0), "r"(b1));
}

__device__ __forceinline__ void ldm4(uint32_t* r, uint32_t saddr) {
    asm volatile("ldmatrix.sync.aligned.m8n8.x4.shared.b16 {%0,%1,%2,%3}, [%4];"
                 : "=r"(r[0]), "=r"(r[1]), "=r"(r[2]), "=r"(r[3]) : "r"(saddr));
}

__device__ __forceinline__ void cpa16(uint32_t s, const void* g) {
    uint64_t ga;
    asm("cvta.to.global.u64 %0, %1;" : "=l"(ga) : "l"(g));
    asm volatile("cp.async.cg.shared.global [%0], [%1], 16;" :: "r"(s), "l"(ga));
}
#define CP_COMMIT() asm volatile("cp.async.commit_group;" ::: "memory")
#define CP_WAIT(n)  asm volatile("cp.async.wait_group %0;" :: "n"(n) : "memory")

__device__ __forceinline__ uint32_t smem_u32(const void* p) {
    return (uint32_t)__cvta_generic_to_shared(p);
}

// ---------------------------------------------------------------------------
// Kernel 1: fused QKV projection (SIMT fp32 core, known good) with split
// epilogue: Q,K -> bf16 hi/lo (Q pre-scaled); V -> fp32 [bh][n][d].
// ---------------------------------------------------------------------------
__global__ __launch_bounds__(256) void qkv_gemm(const float* __restrict__ x,
                                                const float* __restrict__ W,
                                                const float* __restrict__ bias) {
    __shared__ float As[32][65];
    __shared__ float Bs[32][64];

    const int tid = threadIdx.x;
    const int m0 = blockIdx.x * 64;
    const int n0 = blockIdx.y * 64;
    const int tx = tid & 15, ty = tid >> 4;
    const int xr = tid >> 3, xk = (tid & 7) << 2;
    const int wr = tid >> 4, wc = (tid & 15) << 2;

    float c[4][4] = {};
    for (int k0 = 0; k0 < 256; k0 += 32) {
        #pragma unroll
        for (int rr = 0; rr < 64; rr += 32) {
            float4 v = *reinterpret_cast<const float4*>(
                &x[(size_t)(m0 + xr + rr) * 256 + k0 + xk]);
            As[xk + 0][xr + rr] = v.x; As[xk + 1][xr + rr] = v.y;
            As[xk + 2][xr + rr] = v.z; As[xk + 3][xr + rr] = v.w;
        }
        #pragma unroll
        for (int rr = 0; rr < 32; rr += 16)
            *reinterpret_cast<float4*>(&Bs[wr + rr][wc]) =
                *reinterpret_cast<const float4*>(&W[(size_t)(k0 + wr + rr) * 768 + n0 + wc]);
        __syncthreads();
        #pragma unroll
        for (int kk = 0; kk < 32; kk++) {
            float a[4], b[4];
            float4 bv = *reinterpret_cast<const float4*>(&Bs[kk][tx << 2]);
            b[0] = bv.x; b[1] = bv.y; b[2] = bv.z; b[3] = bv.w;
            #pragma unroll
            for (int i = 0; i < 4; i++) a[i] = As[kk][(ty << 2) + i];
            #pragma unroll
            for (int i = 0; i < 4; i++)
                #pragma unroll
                for (int j = 0; j < 4; j++) c[i][j] += a[i] * b[j];
        }
        __syncthreads();
    }

    const int n3b = n0 + (tx << 2);       // 4 consecutive outputs, same head
    const int which = n3b >> 8;           // 0=Q 1=K 2=V
    const int cc = n3b & 255;
    const int h = cc >> 5, d = cc & 31;
    float b0 = bias[n3b], b1 = bias[n3b + 1], b2 = bias[n3b + 2], b3 = bias[n3b + 3];

    #pragma unroll
    for (int i = 0; i < 4; i++) {
        const int m = m0 + (ty << 2) + i;
        const int bb = m >> 11, n = m & 2047;
        float v0 = c[i][0] + b0, v1 = c[i][1] + b1;
        float v2 = c[i][2] + b2, v3 = c[i][3] + b3;
        const size_t idx = ((size_t)(bb * NHEAD + h) * SEQ + n) * HD + d;
        if (which == 0) {
            v0 *= QK_SCALE; v1 *= QK_SCALE; v2 *= QK_SCALE; v3 *= QK_SCALE;
            uint32_t h0, l0, h1, l1;
            split_pack(v0, v1, h0, l0);
            split_pack(v2, v3, h1, l1);
            *reinterpret_cast<uint2*>(&g_qh[idx]) = make_uint2(h0, h1);
            *reinterpret_cast<uint2*>(&g_ql[idx]) = make_uint2(l0, l1);
        } else if (which == 1) {
            uint32_t h0, l0, h1, l1;
            split_pack(v0, v1, h0, l0);
            split_pack(v2, v3, h1, l1);
            *reinterpret_cast<uint2*>(&g_kh[idx]) = make_uint2(h0, h1);
            *reinterpret_cast<uint2*>(&g_kl[idx]) = make_uint2(l0, l1);
        } else {
            *reinterpret_cast<float4*>(&g_v[idx]) = make_float4(v0, v1, v2, v3);
        }
    }
}

// ---------------------------------------------------------------------------
// Kernel 2: V transpose + split:  g_v[bh][n][d] -> g_vth/g_vtl[bh][d][n]
// grid (16 n-blocks, 32 bh), 256 threads
// ---------------------------------------------------------------------------
__global__ __launch_bounds__(256) void vtrans() {
    __shared__ float Vs[32][133];
    const int tid = threadIdx.x;
    const int bh = blockIdx.y;
    const int n0 = blockIdx.x * 128;
    const float* Vp = g_v + ((size_t)bh * SEQ + n0) * HD;

    #pragma unroll
    for (int p = 0; p < 4; p++) {
        const int row = p * 32 + (tid >> 3);
        const int c0 = (tid & 7) << 2;
        float4 v = *reinterpret_cast<const float4*>(&Vp[(size_t)row * HD + c0]);
        Vs[c0 + 0][row] = v.x; Vs[c0 + 1][row] = v.y;
        Vs[c0 + 2][row] = v.z; Vs[c0 + 3][row] = v.w;
    }
    __syncthreads();

    const int d = tid >> 3;
    const int seg = (tid & 7) << 4;
    uint32_t hw[8], lw[8];
    #pragma unroll
    for (int j = 0; j < 8; j++)
        split_pack(Vs[d][seg + 2 * j], Vs[d][seg + 2 * j + 1], hw[j], lw[j]);
    const size_t ob = ((size_t)bh * HD + d) * SEQ + n0 + seg;
    *reinterpret_cast<uint4*>(&g_vth[ob])     = make_uint4(hw[0], hw[1], hw[2], hw[3]);
    *reinterpret_cast<uint4*>(&g_vth[ob + 8]) = make_uint4(hw[4], hw[5], hw[6], hw[7]);
    *reinterpret_cast<uint4*>(&g_vtl[ob])     = make_uint4(lw[0], lw[1], lw[2], lw[3]);
    *reinterpret_cast<uint4*>(&g_vtl[ob + 8]) = make_uint4(lw[4], lw[5], lw[6], lw[7]);
}

// ---------------------------------------------------------------------------
// Kernel 3: flash attention via mma.sync bf16 (3-term split), no-max softmax.
// CTA = 128 thr (4 warps), q-tile 64 rows (16/warp), k-tile 64, cp.async x2.
// ---------------------------------------------------------------------------
#define KSTR 40   // K smem row stride (bf16)
#define VSTR 72   // VT smem row stride (bf16)

__global__ __launch_bounds__(128) void flash_attn(float* __restrict__ out) {
    __shared__ __nv_bfloat16 sKh[2][64 * KSTR];
    __shared__ __nv_bfloat16 sKl[2][64 * KSTR];
    __shared__ __nv_bfloat16 sVh[2][32 * VSTR];
    __shared__ __nv_bfloat16 sVl[2][32 * VSTR];

    const int tid  = threadIdx.x;
    const int lane = tid & 31;
    const int wid  = tid >> 5;
    const int qt   = 31 - blockIdx.x;     // heavy (long) tiles first
    const int bh   = blockIdx.y;
    const int b    = bh >> 3, h = bh & 7;

    const uint32_t aKh[2] = { smem_u32(sKh[0]), smem_u32(sKh[1]) };
    const uint32_t aKl[2] = { smem_u32(sKl[0]), smem_u32(sKl[1]) };
    const uint32_t aVh[2] = { smem_u32(sVh[0]), smem_u32(sVh[1]) };
    const uint32_t aVl[2] = { smem_u32(sVl[0]), smem_u32(sVl[1]) };

    // ---- Q fragments from gmem (persist in registers) ----
    uint32_t qh[2][4], ql[2][4];
    {
        const size_t qbase = ((size_t)bh * SEQ + qt * 64 + wid * 16) * HD;
        const uint32_t* qhp = reinterpret_cast<const uint32_t*>(g_qh) + qbase / 2;
        const uint32_t* qlp = reinterpret_cast<const uint32_t*>(g_ql) + qbase / 2;
        const int r = lane >> 2, t4 = lane & 3;
        #pragma unroll
        for (int kk = 0; kk < 2; kk++) {
            qh[kk][0] = qhp[r * 16 + kk * 8 + t4];
            qh[kk][1] = qhp[(r + 8) * 16 + kk * 8 + t4];
            qh[kk][2] = qhp[r * 16 + kk * 8 + 4 + t4];
            qh[kk][3] = qhp[(r + 8) * 16 + kk * 8 + 4 + t4];
            ql[kk][0] = qlp[r * 16 + kk * 8 + t4];
            ql[kk][1] = qlp[(r + 8) * 16 + kk * 8 + t4];
            ql[kk][2] = qlp[r * 16 + kk * 8 + 4 + t4];
            ql[kk][3] = qlp[(r + 8) * 16 + kk * 8 + 4 + t4];
        }
    }

    const int nkt = (qt < 16) ? 16 : (qt + 1);
    float o[4][4] = {};
    float l0 = 0.f, l1 = 0.f;

    // tile loader (cp.async)
    auto load_tiles = [&](int st, int kt) {
        {   // K hi/lo: row = tid/2 (64 rows), 32B segment = (tid&1)*16 bf16
            const int row = tid >> 1, seg = (tid & 1) << 4;
            const size_t gk = ((size_t)bh * SEQ + kt * 64 + row) * HD + seg;
            const uint32_t sk = (uint32_t)(row * KSTR + seg) * 2;
            cpa16(aKh[st] + sk,      g_kh + gk);
            cpa16(aKh[st] + sk + 16, g_kh + gk + 8);
            cpa16(aKl[st] + sk,      g_kl + gk);
            cpa16(aKl[st] + sk + 16, g_kl + gk + 8);
        }
        {   // VT hi/lo: row d = tid/4 (32 rows), 32B segment = (tid&3)*16 keys
            const int dr = tid >> 2, seg = (tid & 3) << 4;
            const size_t gv = ((size_t)bh * HD + dr) * SEQ + kt * 64 + seg;
            const uint32_t sv = (uint32_t)(dr * VSTR + seg) * 2;
            cpa16(aVh[st] + sv,      g_vth + gv);
            cpa16(aVh[st] + sv + 16, g_vth + gv + 8);
            cpa16(aVl[st] + sv,      g_vtl + gv);
            cpa16(aVl[st] + sv + 16, g_vtl + gv + 8);
        }
    };

    load_tiles(0, 0);
    CP_COMMIT();

    const int r4 = lane >> 2, t4 = lane & 3;
    const int lm_row = lane & 7, lm_cb = lane >> 3;   // ldmatrix lane mapping

    for (int kt = 0; kt < nkt; kt++) {
        if (kt + 1 < nkt) { load_tiles((kt + 1) & 1, kt + 1); CP_COMMIT(); CP_WAIT(1); }
        else              { CP_WAIT(0); }
        __syncthreads();

        const int st = kt & 1;

        // ---- S = Q K^T (3-term) ----
        float s[8][4];
        #pragma unroll
        for (int j = 0; j < 8; j++) { s[j][0] = s[j][1] = s[j][2] = s[j][3] = 0.f; }

        #pragma unroll
        for (int j = 0; j < 8; j++) {
            uint32_t kh[4], kl[4];
            const uint32_t off = (uint32_t)((j * 8 + lm_row) * KSTR + lm_cb * 8) * 2;
            ldm4(kh, aKh[st] + off);
            ldm4(kl, aKl[st] + off);
            mma16816(s[j], qh[0], kh[0], kh[1]);
            mma16816(s[j], qh[1], kh[2], kh[3]);
            mma16816(s[j], qh[0], kl[0], kl[1]);
            mma16816(s[j], qh[1], kl[2], kl[3]);
            mma16816(s[j], ql[0], kh[0], kh[1]);
            mma16816(s[j], ql[1], kh[2], kh[3]);
        }

        // ---- exp (no max-subtraction), diagonal masking, row sums ----
        const bool diag = (qt >= 16) && (kt == qt);
        #pragma unroll
        for (int j = 0; j < 8; j++) {
            float p0 = __expf(s[j][0]), p1 = __expf(s[j][1]);
            float p2 = __expf(s[j][2]), p3 = __expf(s[j][3]);
            if (diag) {
                const int key0 = kt * 64 + j * 8 + t4 * 2;
                const int r0 = qt * 64 + wid * 16 + r4;
                if (key0     > r0)     p0 = 0.f;
                if (key0 + 1 > r0)     p1 = 0.f;
                if (key0     > r0 + 8) p2 = 0.f;
                if (key0 + 1 > r0 + 8) p3 = 0.f;
            }
            l0 += p0 + p1; l1 += p2 + p3;
            s[j][0] = p0; s[j][1] = p1; s[j][2] = p2; s[j][3] = p3;
        }

        // ---- repack P accum frags -> A frags (hi/lo) ----
        uint32_t ah[4][4], al[4][4];
        #pragma unroll
        for (int kk = 0; kk < 4; kk++) {
            const int j0 = 2 * kk, j1 = 2 * kk + 1;
            split_pack(s[j0][0], s[j0][1], ah[kk][0], al[kk][0]);
            split_pack(s[j0][2], s[j0][3], ah[kk][1], al[kk][1]);
            split_pack(s[j1][0], s[j1][1], ah[kk][2], al[kk][2]);
            split_pack(s[j1][2], s[j1][3], ah[kk][3], al[kk][3]);
        }

        // ---- O += P V (3-term) ----
        #pragma unroll
        for (int nd = 0; nd < 4; nd++) {
            uint32_t vh[8], vl[8];
            const uint32_t ro = (uint32_t)((nd * 8 + lm_row) * VSTR) * 2;
            ldm4(vh,     aVh[st] + ro + (uint32_t)(lm_cb * 8) * 2);
            ldm4(vh + 4, aVh[st] + ro + (uint32_t)(32 + lm_cb * 8) * 2);
            ldm4(vl,     aVl[st] + ro + (uint32_t)(lm_cb * 8) * 2);
            ldm4(vl + 4, aVl[st] + ro + (uint32_t)(32 + lm_cb * 8) * 2);
            #pragma unroll
            for (int kk = 0; kk < 4; kk++) {
                mma16816(o[nd], ah[kk], vh[2 * kk], vh[2 * kk + 1]);
                mma16816(o[nd], al[kk], vh[2 * kk], vh[2 * kk + 1]);
                mma16816(o[nd], ah[kk], vl[2 * kk], vl[2 * kk + 1]);
            }
        }
        __syncthreads();
    }

    // ---- finalize: divide by row sums, write out ----
    l0 += __shfl_xor_sync(0xffffffffu, l0, 1);
    l0 += __shfl_xor_sync(0xffffffffu, l0, 2);
    l1 += __shfl_xor_sync(0xffffffffu, l1, 1);
    l1 += __shfl_xor_sync(0xffffffffu, l1, 2);
    const float inv0 = 1.f / l0, inv1 = 1.f / l1;

    const int row0 = qt * 64 + wid * 16 + r4;
    #pragma unroll
    for (int nd = 0; nd < 4; nd++) {
        const int d0 = nd * 8 + t4 * 2;
        const size_t o0 = ((size_t)(b * SEQ + row0)) * DIM + h * HD + d0;
        const size_t o1 = ((size_t)(b * SEQ + row0 + 8)) * DIM + h * HD + d0;
        *reinterpret_cast<float2*>(&out[o0]) = make_float2(o[nd][0] * inv0, o[nd][1] * inv0);
        *reinterpret_cast<float2*>(&out[o1]) = make_float2(o[nd][2] * inv1, o[nd][3] * inv1);
    }
}

extern "C" void kernel_launch(void* const* d_in, const int* in_sizes, int n_in,
                              void* d_out, int out_size) {
    const float* x    = (const float*)d_in[0];
    const float* W    = (const float*)d_in[1];
    const float* bias = (const float*)d_in[2];
    float* out = (float*)d_out;

    dim3 gemm_grid(8192 / 64, 768 / 64);
    qkv_gemm<<<gemm_grid, 256>>>(x, W, bias);

    dim3 vt_grid(16, 32);
    vtrans<<<vt_grid, 256>>>();

    dim3 attn_grid(32, 32);
    flash_attn<<<attn_grid, 128>>>(out);
}

// round 7
// speedup vs baseline: 2.9101x; 1.2020x over previous
#include <cuda_runtime.h>
#include <cuda_bf16.h>
#include <cstdint>

#define SEQ     2048
#define DIM     256
#define NHEAD   8
#define HD      32
#define NBATCH  4
#define NBH     (NBATCH * NHEAD)
#define QK_SCALE 0.17677669529663687f   // 32^-0.5

// bf16 hi/lo split scratch
__device__ __align__(16) __nv_bfloat16 g_qh[NBH * SEQ * HD];
__device__ __align__(16) __nv_bfloat16 g_ql[NBH * SEQ * HD];
__device__ __align__(16) __nv_bfloat16 g_kh[NBH * SEQ * HD];
__device__ __align__(16) __nv_bfloat16 g_kl[NBH * SEQ * HD];
__device__ __align__(16) float         g_v [NBH * SEQ * HD];   // fp32, [bh][n][d]
__device__ __align__(16) __nv_bfloat16 g_vth[NBH * HD * SEQ];  // V^T hi, [bh][d][n]
__device__ __align__(16) __nv_bfloat16 g_vtl[NBH * HD * SEQ];  // V^T lo
// pre-split GEMM operands
__device__ __align__(16) __nv_bfloat16 g_xh[8192 * 256];       // x hi, [m][k]
__device__ __align__(16) __nv_bfloat16 g_xl[8192 * 256];       // x lo
__device__ __align__(16) __nv_bfloat16 g_wh[768 * 256];        // W^T hi, [n][k]
__device__ __align__(16) __nv_bfloat16 g_wl[768 * 256];        // W^T lo

// ---------------------------------------------------------------------------
// helpers
// ---------------------------------------------------------------------------
__device__ __forceinline__ void split_pack(float x0, float x1,
                                           uint32_t& h, uint32_t& l) {
    uint32_t hp;
    asm("cvt.rn.bf16x2.f32 %0, %1, %2;" : "=r"(hp) : "f"(x1), "f"(x0));
    float h0 = __uint_as_float(hp << 16);
    float h1 = __uint_as_float(hp & 0xFFFF0000u);
    h = hp;
    asm("cvt.rn.bf16x2.f32 %0, %1, %2;" : "=r"(l) : "f"(x1 - h1), "f"(x0 - h0));
}

__device__ __forceinline__ void mma16816(float* c, const uint32_t* a,
                                         uint32_t b0, uint32_t b1) {
    asm volatile(
        "mma.sync.aligned.m16n8k16.row.col.f32.bf16.bf16.f32 "
        "{%0,%1,%2,%3}, {%4,%5,%6,%7}, {%8,%9}, {%0,%1,%2,%3};"
        : "+f"(c[0]), "+f"(c[1]), "+f"(c[2]), "+f"(c[3])
        : "r"(a[0]), "r"(a[1]), "r"(a[2]), "r"(a[3]), "r"(b0), "r"(b1));
}

__device__ __forceinline__ void ldm4(uint32_t* r, uint32_t saddr) {
    asm volatile("ldmatrix.sync.aligned.m8n8.x4.shared.b16 {%0,%1,%2,%3}, [%4];"
                 : "=r"(r[0]), "=r"(r[1]), "=r"(r[2]), "=r"(r[3]) : "r"(saddr));
}

__device__ __forceinline__ void cpa16(uint32_t s, const void* g) {
    uint64_t ga;
    asm("cvta.to.global.u64 %0, %1;" : "=l"(ga) : "l"(g));
    asm volatile("cp.async.cg.shared.global [%0], [%1], 16;" :: "r"(s), "l"(ga));
}
#define CP_COMMIT() asm volatile("cp.async.commit_group;" ::: "memory")
#define CP_WAIT(n)  asm volatile("cp.async.wait_group %0;" :: "n"(n) : "memory")

__device__ __forceinline__ uint32_t smem_u32(const void* p) {
    return (uint32_t)__cvta_generic_to_shared(p);
}

// ---------------------------------------------------------------------------
// Prep A: split x -> bf16 hi/lo
// ---------------------------------------------------------------------------
__global__ __launch_bounds__(256) void xsplit(const float* __restrict__ x) {
    const size_t e0 = ((size_t)blockIdx.x * 256 + threadIdx.x) * 4;
    float4 v = *reinterpret_cast<const float4*>(&x[e0]);
    uint32_t h0, l0, h1, l1;
    split_pack(v.x, v.y, h0, l0);
    split_pack(v.z, v.w, h1, l1);
    *reinterpret_cast<uint2*>(&g_xh[e0]) = make_uint2(h0, h1);
    *reinterpret_cast<uint2*>(&g_xl[e0]) = make_uint2(l0, l1);
}

// ---------------------------------------------------------------------------
// Prep B: transpose + split W [k=256][n=768] -> W^T hi/lo [n][k]
// grid (12 n-tiles of 64, 4 k-tiles of 64), 256 threads
// ---------------------------------------------------------------------------
__global__ __launch_bounds__(256) void wsplit(const float* __restrict__ W) {
    __shared__ float Ws[64][65];
    const int tid = threadIdx.x;
    const int n0 = blockIdx.x * 64;
    const int k0 = blockIdx.y * 64;

    const int kr = tid >> 2, nc = (tid & 3) << 4;
    #pragma unroll
    for (int j = 0; j < 4; j++) {
        float4 v = *reinterpret_cast<const float4*>(&W[(size_t)(k0 + kr) * 768 + n0 + nc + j * 4]);
        Ws[kr][nc + j * 4 + 0] = v.x; Ws[kr][nc + j * 4 + 1] = v.y;
        Ws[kr][nc + j * 4 + 2] = v.z; Ws[kr][nc + j * 4 + 3] = v.w;
    }
    __syncthreads();

    const int nr = tid >> 2, ks = (tid & 3) << 4;
    uint32_t hw[8], lw[8];
    #pragma unroll
    for (int j = 0; j < 8; j++)
        split_pack(Ws[ks + 2 * j][nr], Ws[ks + 2 * j + 1][nr], hw[j], lw[j]);
    const size_t ob = (size_t)(n0 + nr) * 256 + k0 + ks;
    *reinterpret_cast<uint4*>(&g_wh[ob])     = make_uint4(hw[0], hw[1], hw[2], hw[3]);
    *reinterpret_cast<uint4*>(&g_wh[ob + 8]) = make_uint4(hw[4], hw[5], hw[6], hw[7]);
    *reinterpret_cast<uint4*>(&g_wl[ob])     = make_uint4(lw[0], lw[1], lw[2], lw[3]);
    *reinterpret_cast<uint4*>(&g_wl[ob + 8]) = make_uint4(lw[4], lw[5], lw[6], lw[7]);
}

// ---------------------------------------------------------------------------
// Kernel: QKV GEMM via mma.sync bf16 3-term.  CTA 128x128, 8 warps (2m x 4n),
// warp tile 64x32, k-chunk 32, cp.async double buffer.
// Epilogue scatters Q/K (bf16 split, Q scaled) and V (fp32).
// ---------------------------------------------------------------------------
#define ASTR 40
#define TILEB (128 * ASTR)   // bf16 elems per buffer

__global__ __launch_bounds__(256) void qkv_mma(const float* __restrict__ bias) {
    extern __shared__ __nv_bfloat16 sm[];
    // layout: [stage][ah, al, bh, bl]
    __nv_bfloat16* sAh[2] = { sm,             sm + 4 * TILEB };
    __nv_bfloat16* sAl[2] = { sm + 1 * TILEB, sm + 5 * TILEB };
    __nv_bfloat16* sBh[2] = { sm + 2 * TILEB, sm + 6 * TILEB };
    __nv_bfloat16* sBl[2] = { sm + 3 * TILEB, sm + 7 * TILEB };

    const int tid  = threadIdx.x;
    const int lane = tid & 31;
    const int wid  = tid >> 5;
    const int wm = wid & 1, wn = wid >> 1;
    const int m0 = blockIdx.x * 128;
    const int n0 = blockIdx.y * 128;

    // cp.async mapping: row = tid>>1 (128 rows), 32B seg = (tid&1)*16 elems
    const int crow = tid >> 1, cseg = (tid & 1) << 4;
    const uint32_t soff = (uint32_t)(crow * ASTR + cseg) * 2;

    auto load_stage = [&](int st, int kc) {
        const size_t ga = (size_t)(m0 + crow) * 256 + kc * 32 + cseg;
        const size_t gb = (size_t)(n0 + crow) * 256 + kc * 32 + cseg;
        uint32_t ah = smem_u32(sAh[st]) + soff;
        uint32_t al = smem_u32(sAl[st]) + soff;
        uint32_t bh = smem_u32(sBh[st]) + soff;
        uint32_t bl = smem_u32(sBl[st]) + soff;
        cpa16(ah, g_xh + ga); cpa16(ah + 16, g_xh + ga + 8);
        cpa16(al, g_xl + ga); cpa16(al + 16, g_xl + ga + 8);
        cpa16(bh, g_wh + gb); cpa16(bh + 16, g_wh + gb + 8);
        cpa16(bl, g_wl + gb); cpa16(bl + 16, g_wl + gb + 8);
    };

    float c[4][4][4];
    #pragma unroll
    for (int mi = 0; mi < 4; mi++)
        #pragma unroll
        for (int j = 0; j < 4; j++)
            { c[mi][j][0] = c[mi][j][1] = c[mi][j][2] = c[mi][j][3] = 0.f; }

    // ldmatrix addressing
    // A (m16k16): rows lane&15, col (lane>>4)*8  -> canonical a0..a3
    const int a_r = (lane & 7) + ((lane >> 3) & 1) * 8;
    const int a_c = (lane >> 4) * 8;
    // B (n8 x k32, attention-style): rows j*8 + (lane&7), col (lane>>3)*8
    const int b_r = lane & 7;
    const int b_c = (lane >> 3) * 8;

    load_stage(0, 0);
    CP_COMMIT();

    for (int kc = 0; kc < 8; kc++) {
        if (kc + 1 < 8) { load_stage((kc + 1) & 1, kc + 1); CP_COMMIT(); CP_WAIT(1); }
        else            { CP_WAIT(0); }
        __syncthreads();
        const int st = kc & 1;

        // B frags: 4 n8 groups, each k0-31 (4 regs) hi+lo
        uint32_t bh[4][4], bl[4][4];
        const uint32_t bbase_h = smem_u32(sBh[st]);
        const uint32_t bbase_l = smem_u32(sBl[st]);
        #pragma unroll
        for (int j = 0; j < 4; j++) {
            const uint32_t off = (uint32_t)((wn * 32 + j * 8 + b_r) * ASTR + b_c) * 2;
            ldm4(bh[j], bbase_h + off);
            ldm4(bl[j], bbase_l + off);
        }

        const uint32_t abase_h = smem_u32(sAh[st]);
        const uint32_t abase_l = smem_u32(sAl[st]);
        #pragma unroll
        for (int mi = 0; mi < 4; mi++) {
            uint32_t ah[2][4], al[2][4];
            #pragma unroll
            for (int kk = 0; kk < 2; kk++) {
                const uint32_t off =
                    (uint32_t)((wm * 64 + mi * 16 + a_r) * ASTR + kk * 16 + a_c) * 2;
                ldm4(ah[kk], abase_h + off);
                ldm4(al[kk], abase_l + off);
            }
            #pragma unroll
            for (int j = 0; j < 4; j++) {
                mma16816(c[mi][j], ah[0], bh[j][0], bh[j][1]);   // hi*hi k0-15
                mma16816(c[mi][j], ah[1], bh[j][2], bh[j][3]);   // hi*hi k16-31
                mma16816(c[mi][j], ah[0], bl[j][0], bl[j][1]);   // hi*lo
                mma16816(c[mi][j], ah[1], bl[j][2], bl[j][3]);
                mma16816(c[mi][j], al[0], bh[j][0], bh[j][1]);   // lo*hi
                mma16816(c[mi][j], al[1], bh[j][2], bh[j][3]);
            }
        }
        __syncthreads();
    }

    // ---- epilogue: bias + scatter (which is uniform per CTA) ----
    const int which = n0 >> 8;            // 0=Q 1=K 2=V
    const int r4 = lane >> 2, t4 = lane & 3;
    #pragma unroll
    for (int j = 0; j < 4; j++) {
        const int n3 = n0 + wn * 32 + j * 8 + t4 * 2;
        const int cc = n3 & 255, h = cc >> 5, d = cc & 31;
        const float b0 = __ldg(&bias[n3]), b1 = __ldg(&bias[n3 + 1]);
        #pragma unroll
        for (int mi = 0; mi < 4; mi++) {
            #pragma unroll
            for (int half = 0; half < 2; half++) {
                const int m = m0 + wm * 64 + mi * 16 + r4 + half * 8;
                const int bb = m >> 11, n = m & 2047;
                float v0 = c[mi][j][2 * half + 0] + b0;
                float v1 = c[mi][j][2 * half + 1] + b1;
                const size_t idx = ((size_t)(bb * NHEAD + h) * SEQ + n) * HD + d;
                if (which == 0) {
                    v0 *= QK_SCALE; v1 *= QK_SCALE;
                    uint32_t hw, lw;
                    split_pack(v0, v1, hw, lw);
                    *reinterpret_cast<uint32_t*>(&g_qh[idx]) = hw;
                    *reinterpret_cast<uint32_t*>(&g_ql[idx]) = lw;
                } else if (which == 1) {
                    uint32_t hw, lw;
                    split_pack(v0, v1, hw, lw);
                    *reinterpret_cast<uint32_t*>(&g_kh[idx]) = hw;
                    *reinterpret_cast<uint32_t*>(&g_kl[idx]) = lw;
                } else {
                    *reinterpret_cast<float2*>(&g_v[idx]) = make_float2(v0, v1);
                }
            }
        }
    }
}

// ---------------------------------------------------------------------------
// V transpose + split:  g_v[bh][n][d] -> g_vth/g_vtl[bh][d][n]
// ---------------------------------------------------------------------------
__global__ __launch_bounds__(256) void vtrans() {
    __shared__ float Vs[32][133];
    const int tid = threadIdx.x;
    const int bh = blockIdx.y;
    const int n0 = blockIdx.x * 128;
    const float* Vp = g_v + ((size_t)bh * SEQ + n0) * HD;

    #pragma unroll
    for (int p = 0; p < 4; p++) {
        const int row = p * 32 + (tid >> 3);
        const int c0 = (tid & 7) << 2;
        float4 v = *reinterpret_cast<const float4*>(&Vp[(size_t)row * HD + c0]);
        Vs[c0 + 0][row] = v.x; Vs[c0 + 1][row] = v.y;
        Vs[c0 + 2][row] = v.z; Vs[c0 + 3][row] = v.w;
    }
    __syncthreads();

    const int d = tid >> 3;
    const int seg = (tid & 7) << 4;
    uint32_t hw[8], lw[8];
    #pragma unroll
    for (int j = 0; j < 8; j++)
        split_pack(Vs[d][seg + 2 * j], Vs[d][seg + 2 * j + 1], hw[j], lw[j]);
    const size_t ob = ((size_t)bh * HD + d) * SEQ + n0 + seg;
    *reinterpret_cast<uint4*>(&g_vth[ob])     = make_uint4(hw[0], hw[1], hw[2], hw[3]);
    *reinterpret_cast<uint4*>(&g_vth[ob + 8]) = make_uint4(hw[4], hw[5], hw[6], hw[7]);
    *reinterpret_cast<uint4*>(&g_vtl[ob])     = make_uint4(lw[0], lw[1], lw[2], lw[3]);
    *reinterpret_cast<uint4*>(&g_vtl[ob + 8]) = make_uint4(lw[4], lw[5], lw[6], lw[7]);
}

// ---------------------------------------------------------------------------
// Flash attention via mma.sync bf16 (3-term split), no-max softmax.
// (unchanged from R5 — validated at rel_err 6.4e-6)
// ---------------------------------------------------------------------------
#define KSTR 40
#define VSTR 72

__global__ __launch_bounds__(128) void flash_attn(float* __restrict__ out) {
    __shared__ __nv_bfloat16 sKh[2][64 * KSTR];
    __shared__ __nv_bfloat16 sKl[2][64 * KSTR];
    __shared__ __nv_bfloat16 sVh[2][32 * VSTR];
    __shared__ __nv_bfloat16 sVl[2][32 * VSTR];

    const int tid  = threadIdx.x;
    const int lane = tid & 31;
    const int wid  = tid >> 5;
    const int qt   = 31 - blockIdx.x;
    const int bh   = blockIdx.y;
    const int b    = bh >> 3, h = bh & 7;

    const uint32_t aKh[2] = { smem_u32(sKh[0]), smem_u32(sKh[1]) };
    const uint32_t aKl[2] = { smem_u32(sKl[0]), smem_u32(sKl[1]) };
    const uint32_t aVh[2] = { smem_u32(sVh[0]), smem_u32(sVh[1]) };
    const uint32_t aVl[2] = { smem_u32(sVl[0]), smem_u32(sVl[1]) };

    uint32_t qh[2][4], ql[2][4];
    {
        const size_t qbase = ((size_t)bh * SEQ + qt * 64 + wid * 16) * HD;
        const uint32_t* qhp = reinterpret_cast<const uint32_t*>(g_qh) + qbase / 2;
        const uint32_t* qlp = reinterpret_cast<const uint32_t*>(g_ql) + qbase / 2;
        const int r = lane >> 2, t4 = lane & 3;
        #pragma unroll
        for (int kk = 0; kk < 2; kk++) {
            qh[kk][0] = qhp[r * 16 + kk * 8 + t4];
            qh[kk][1] = qhp[(r + 8) * 16 + kk * 8 + t4];
            qh[kk][2] = qhp[r * 16 + kk * 8 + 4 + t4];
            qh[kk][3] = qhp[(r + 8) * 16 + kk * 8 + 4 + t4];
            ql[kk][0] = qlp[r * 16 + kk * 8 + t4];
            ql[kk][1] = qlp[(r + 8) * 16 + kk * 8 + t4];
            ql[kk][2] = qlp[r * 16 + kk * 8 + 4 + t4];
            ql[kk][3] = qlp[(r + 8) * 16 + kk * 8 + 4 + t4];
        }
    }

    const int nkt = (qt < 16) ? 16 : (qt + 1);
    float o[4][4] = {};
    float l0 = 0.f, l1 = 0.f;

    auto load_tiles = [&](int st, int kt) {
        {
            const int row = tid >> 1, seg = (tid & 1) << 4;
            const size_t gk = ((size_t)bh * SEQ + kt * 64 + row) * HD + seg;
            const uint32_t sk = (uint32_t)(row * KSTR + seg) * 2;
            cpa16(aKh[st] + sk,      g_kh + gk);
            cpa16(aKh[st] + sk + 16, g_kh + gk + 8);
            cpa16(aKl[st] + sk,      g_kl + gk);
            cpa16(aKl[st] + sk + 16, g_kl + gk + 8);
        }
        {
            const int dr = tid >> 2, seg = (tid & 3) << 4;
            const size_t gv = ((size_t)bh * HD + dr) * SEQ + kt * 64 + seg;
            const uint32_t sv = (uint32_t)(dr * VSTR + seg) * 2;
            cpa16(aVh[st] + sv,      g_vth + gv);
            cpa16(aVh[st] + sv + 16, g_vth + gv + 8);
            cpa16(aVl[st] + sv,      g_vtl + gv);
            cpa16(aVl[st] + sv + 16, g_vtl + gv + 8);
        }
    };

    load_tiles(0, 0);
    CP_COMMIT();

    const int r4 = lane >> 2, t4 = lane & 3;
    const int lm_row = lane & 7, lm_cb = lane >> 3;

    for (int kt = 0; kt < nkt; kt++) {
        if (kt + 1 < nkt) { load_tiles((kt + 1) & 1, kt + 1); CP_COMMIT(); CP_WAIT(1); }
        else              { CP_WAIT(0); }
        __syncthreads();

        const int st = kt & 1;

        float s[8][4];
        #pragma unroll
        for (int j = 0; j < 8; j++) { s[j][0] = s[j][1] = s[j][2] = s[j][3] = 0.f; }

        #pragma unroll
        for (int j = 0; j < 8; j++) {
            uint32_t kh[4], kl[4];
            const uint32_t off = (uint32_t)((j * 8 + lm_row) * KSTR + lm_cb * 8) * 2;
            ldm4(kh, aKh[st] + off);
            ldm4(kl, aKl[st] + off);
            mma16816(s[j], qh[0], kh[0], kh[1]);
            mma16816(s[j], qh[1], kh[2], kh[3]);
            mma16816(s[j], qh[0], kl[0], kl[1]);
            mma16816(s[j], qh[1], kl[2], kl[3]);
            mma16816(s[j], ql[0], kh[0], kh[1]);
            mma16816(s[j], ql[1], kh[2], kh[3]);
        }

        const bool diag = (qt >= 16) && (kt == qt);
        #pragma unroll
        for (int j = 0; j < 8; j++) {
            float p0 = __expf(s[j][0]), p1 = __expf(s[j][1]);
            float p2 = __expf(s[j][2]), p3 = __expf(s[j][3]);
            if (diag) {
                const int key0 = kt * 64 + j * 8 + t4 * 2;
                const int r0 = qt * 64 + wid * 16 + r4;
                if (key0     > r0)     p0 = 0.f;
                if (key0 + 1 > r0)     p1 = 0.f;
                if (key0     > r0 + 8) p2 = 0.f;
                if (key0 + 1 > r0 + 8) p3 = 0.f;
            }
            l0 += p0 + p1; l1 += p2 + p3;
            s[j][0] = p0; s[j][1] = p1; s[j][2] = p2; s[j][3] = p3;
        }

        uint32_t ah[4][4], al[4][4];
        #pragma unroll
        for (int kk = 0; kk < 4; kk++) {
            const int j0 = 2 * kk, j1 = 2 * kk + 1;
            split_pack(s[j0][0], s[j0][1], ah[kk][0], al[kk][0]);
            split_pack(s[j0][2], s[j0][3], ah[kk][1], al[kk][1]);
            split_pack(s[j1][0], s[j1][1], ah[kk][2], al[kk][2]);
            split_pack(s[j1][2], s[j1][3], ah[kk][3], al[kk][3]);
        }

        #pragma unroll
        for (int nd = 0; nd < 4; nd++) {
            uint32_t vh[8], vl[8];
            const uint32_t ro = (uint32_t)((nd * 8 + lm_row) * VSTR) * 2;
            ldm4(vh,     aVh[st] + ro + (uint32_t)(lm_cb * 8) * 2);
            ldm4(vh + 4, aVh[st] + ro + (uint32_t)(32 + lm_cb * 8) * 2);
            ldm4(vl,     aVl[st] + ro + (uint32_t)(lm_cb * 8) * 2);
            ldm4(vl + 4, aVl[st] + ro + (uint32_t)(32 + lm_cb * 8) * 2);
            #pragma unroll
            for (int kk = 0; kk < 4; kk++) {
                mma16816(o[nd], ah[kk], vh[2 * kk], vh[2 * kk + 1]);
                mma16816(o[nd], al[kk], vh[2 * kk], vh[2 * kk + 1]);
                mma16816(o[nd], ah[kk], vl[2 * kk], vl[2 * kk + 1]);
            }
        }
        __syncthreads();
    }

    l0 += __shfl_xor_sync(0xffffffffu, l0, 1);
    l0 += __shfl_xor_sync(0xffffffffu, l0, 2);
    l1 += __shfl_xor_sync(0xffffffffu, l1, 1);
    l1 += __shfl_xor_sync(0xffffffffu, l1, 2);
    const float inv0 = 1.f / l0, inv1 = 1.f / l1;

    const int row0 = qt * 64 + wid * 16 + r4;
    #pragma unroll
    for (int nd = 0; nd < 4; nd++) {
        const int d0 = nd * 8 + t4 * 2;
        const size_t o0 = ((size_t)(b * SEQ + row0)) * DIM + h * HD + d0;
        const size_t o1 = ((size_t)(b * SEQ + row0 + 8)) * DIM + h * HD + d0;
        *reinterpret_cast<float2*>(&out[o0]) = make_float2(o[nd][0] * inv0, o[nd][1] * inv0);
        *reinterpret_cast<float2*>(&out[o1]) = make_float2(o[nd][2] * inv1, o[nd][3] * inv1);
    }
}

extern "C" void kernel_launch(void* const* d_in, const int* in_sizes, int n_in,
                              void* d_out, int out_size) {
    const float* x    = (const float*)d_in[0];
    const float* W    = (const float*)d_in[1];
    const float* bias = (const float*)d_in[2];
    float* out = (float*)d_out;

    static int init_done = 0;
    if (!init_done) {
        cudaFuncSetAttribute(qkv_mma,
                             cudaFuncAttributeMaxDynamicSharedMemorySize,
                             8 * TILEB * (int)sizeof(__nv_bfloat16));
        init_done = 1;
    }

    xsplit<<<2048, 256>>>(x);
    wsplit<<<dim3(12, 4), 256>>>(W);
    qkv_mma<<<dim3(64, 6), 256, 8 * TILEB * sizeof(__nv_bfloat16)>>>(bias);

    dim3 vt_grid(16, 32);
    vtrans<<<vt_grid, 256>>>();

    dim3 attn_grid(32, 32);
    flash_attn<<<attn_grid, 128>>>(out);
}

// round 8
// speedup vs baseline: 3.9521x; 1.3581x over previous
#include <cuda_runtime.h>
#include <cuda_fp16.h>
#include <cstdint>

#define SEQ     2048
#define DIM     256
#define NHEAD   8
#define HD      32
#define NBATCH  4
#define NBH     (NBATCH * NHEAD)
#define QK_SCALE_L2E (0.17677669529663687f * 1.4426950408889634f)  // 32^-0.5 * log2(e)

// fp16 hi/lo split scratch
__device__ __align__(16) __half g_qh[NBH * SEQ * HD];
__device__ __align__(16) __half g_ql[NBH * SEQ * HD];
__device__ __align__(16) __half g_kh[NBH * SEQ * HD];
__device__ __align__(16) __half g_kl[NBH * SEQ * HD];
__device__ __align__(16) __half g_v16[NBH * SEQ * HD];   // V f16, [bh][n][d]
__device__ __align__(16) __half g_vth[NBH * HD * SEQ];   // V^T f16, [bh][d][n]
// pre-split GEMM operands
__device__ __align__(16) __half g_xh[8192 * 256];        // x hi, [m][k]
__device__ __align__(16) __half g_xl[8192 * 256];        // x lo
__device__ __align__(16) __half g_wh[768 * 256];         // W^T hi, [n][k]
__device__ __align__(16) __half g_wl[768 * 256];         // W^T lo

// ---------------------------------------------------------------------------
// helpers
// ---------------------------------------------------------------------------
__device__ __forceinline__ uint32_t pack_f16(float x0, float x1) {
    __half2 hh = __floats2half2_rn(make_float2(x0, x1).x, make_float2(x0, x1).y);
    return *reinterpret_cast<uint32_t*>(&hh);
}
__device__ __forceinline__ void split_pack_f16(float x0, float x1,
                                               uint32_t& h, uint32_t& l) {
    __half2 hh = __floats2half2_rn(x0, x1);
    float2 hf = __half22float2(hh);
    __half2 ll = __floats2half2_rn(x0 - hf.x, x1 - hf.y);
    h = *reinterpret_cast<uint32_t*>(&hh);
    l = *reinterpret_cast<uint32_t*>(&ll);
}
__device__ __forceinline__ float ex2(float x) {
    float y;
    asm("ex2.approx.f32 %0, %1;" : "=f"(y) : "f"(x));
    return y;
}

__device__ __forceinline__ void mma16816(float* c, const uint32_t* a,
                                         uint32_t b0, uint32_t b1) {
    asm volatile(
        "mma.sync.aligned.m16n8k16.row.col.f32.f16.f16.f32 "
        "{%0,%1,%2,%3}, {%4,%5,%6,%7}, {%8,%9}, {%0,%1,%2,%3};"
        : "+f"(c[0]), "+f"(c[1]), "+f"(c[2]), "+f"(c[3])
        : "r"(a[0]), "r"(a[1]), "r"(a[2]), "r"(a[3]), "r"(b0), "r"(b1));
}

__device__ __forceinline__ void ldm4(uint32_t* r, uint32_t saddr) {
    asm volatile("ldmatrix.sync.aligned.m8n8.x4.shared.b16 {%0,%1,%2,%3}, [%4];"
                 : "=r"(r[0]), "=r"(r[1]), "=r"(r[2]), "=r"(r[3]) : "r"(saddr));
}

__device__ __forceinline__ void cpa16(uint32_t s, const void* g) {
    uint64_t ga;
    asm("cvta.to.global.u64 %0, %1;" : "=l"(ga) : "l"(g));
    asm volatile("cp.async.cg.shared.global [%0], [%1], 16;" :: "r"(s), "l"(ga));
}
#define CP_COMMIT() asm volatile("cp.async.commit_group;" ::: "memory")
#define CP_WAIT(n)  asm volatile("cp.async.wait_group %0;" :: "n"(n) : "memory")

__device__ __forceinline__ uint32_t smem_u32(const void* p) {
    return (uint32_t)__cvta_generic_to_shared(p);
}

// ---------------------------------------------------------------------------
// Prep A: split x -> f16 hi/lo
// ---------------------------------------------------------------------------
__global__ __launch_bounds__(256) void xsplit(const float* __restrict__ x) {
    const size_t e0 = ((size_t)blockIdx.x * 256 + threadIdx.x) * 4;
    float4 v = *reinterpret_cast<const float4*>(&x[e0]);
    uint32_t h0, l0, h1, l1;
    split_pack_f16(v.x, v.y, h0, l0);
    split_pack_f16(v.z, v.w, h1, l1);
    *reinterpret_cast<uint2*>(&g_xh[e0]) = make_uint2(h0, h1);
    *reinterpret_cast<uint2*>(&g_xl[e0]) = make_uint2(l0, l1);
}

// ---------------------------------------------------------------------------
// Prep B: transpose + split W [k=256][n=768] -> W^T hi/lo [n][k]
// ---------------------------------------------------------------------------
__global__ __launch_bounds__(256) void wsplit(const float* __restrict__ W) {
    __shared__ float Ws[64][65];
    const int tid = threadIdx.x;
    const int n0 = blockIdx.x * 64;
    const int k0 = blockIdx.y * 64;

    const int kr = tid >> 2, nc = (tid & 3) << 4;
    #pragma unroll
    for (int j = 0; j < 4; j++) {
        float4 v = *reinterpret_cast<const float4*>(&W[(size_t)(k0 + kr) * 768 + n0 + nc + j * 4]);
        Ws[kr][nc + j * 4 + 0] = v.x; Ws[kr][nc + j * 4 + 1] = v.y;
        Ws[kr][nc + j * 4 + 2] = v.z; Ws[kr][nc + j * 4 + 3] = v.w;
    }
    __syncthreads();

    const int nr = tid >> 2, ks = (tid & 3) << 4;
    uint32_t hw[8], lw[8];
    #pragma unroll
    for (int j = 0; j < 8; j++)
        split_pack_f16(Ws[ks + 2 * j][nr], Ws[ks + 2 * j + 1][nr], hw[j], lw[j]);
    const size_t ob = (size_t)(n0 + nr) * 256 + k0 + ks;
    *reinterpret_cast<uint4*>(&g_wh[ob])     = make_uint4(hw[0], hw[1], hw[2], hw[3]);
    *reinterpret_cast<uint4*>(&g_wh[ob + 8]) = make_uint4(hw[4], hw[5], hw[6], hw[7]);
    *reinterpret_cast<uint4*>(&g_wl[ob])     = make_uint4(lw[0], lw[1], lw[2], lw[3]);
    *reinterpret_cast<uint4*>(&g_wl[ob + 8]) = make_uint4(lw[4], lw[5], lw[6], lw[7]);
}

// ---------------------------------------------------------------------------
// QKV GEMM via mma.sync f16 3-term.  CTA 128x128, 8 warps (2m x 4n),
// warp tile 64x32, k-chunk 32, cp.async double buffer.
// Epilogue scatters Q/K (f16 hi/lo, Q pre-scaled incl log2e) and V (f16).
// ---------------------------------------------------------------------------
#define ASTR 40
#define TILEB (128 * ASTR)   // f16 elems per buffer

__global__ __launch_bounds__(256) void qkv_mma(const float* __restrict__ bias) {
    extern __shared__ __half sm[];
    __half* sAh[2] = { sm,             sm + 4 * TILEB };
    __half* sAl[2] = { sm + 1 * TILEB, sm + 5 * TILEB };
    __half* sBh[2] = { sm + 2 * TILEB, sm + 6 * TILEB };
    __half* sBl[2] = { sm + 3 * TILEB, sm + 7 * TILEB };

    const int tid  = threadIdx.x;
    const int lane = tid & 31;
    const int wid  = tid >> 5;
    const int wm = wid & 1, wn = wid >> 1;
    const int m0 = blockIdx.x * 128;
    const int n0 = blockIdx.y * 128;

    const int crow = tid >> 1, cseg = (tid & 1) << 4;
    const uint32_t soff = (uint32_t)(crow * ASTR + cseg) * 2;

    auto load_stage = [&](int st, int kc) {
        const size_t ga = (size_t)(m0 + crow) * 256 + kc * 32 + cseg;
        const size_t gb = (size_t)(n0 + crow) * 256 + kc * 32 + cseg;
        uint32_t ah = smem_u32(sAh[st]) + soff;
        uint32_t al = smem_u32(sAl[st]) + soff;
        uint32_t bh = smem_u32(sBh[st]) + soff;
        uint32_t bl = smem_u32(sBl[st]) + soff;
        cpa16(ah, g_xh + ga); cpa16(ah + 16, g_xh + ga + 8);
        cpa16(al, g_xl + ga); cpa16(al + 16, g_xl + ga + 8);
        cpa16(bh, g_wh + gb); cpa16(bh + 16, g_wh + gb + 8);
        cpa16(bl, g_wl + gb); cpa16(bl + 16, g_wl + gb + 8);
    };

    float c[4][4][4];
    #pragma unroll
    for (int mi = 0; mi < 4; mi++)
        #pragma unroll
        for (int j = 0; j < 4; j++)
            { c[mi][j][0] = c[mi][j][1] = c[mi][j][2] = c[mi][j][3] = 0.f; }

    const int a_r = (lane & 7) + ((lane >> 3) & 1) * 8;
    const int a_c = (lane >> 4) * 8;
    const int b_r = lane & 7;
    const int b_c = (lane >> 3) * 8;

    load_stage(0, 0);
    CP_COMMIT();

    for (int kc = 0; kc < 8; kc++) {
        if (kc + 1 < 8) { load_stage((kc + 1) & 1, kc + 1); CP_COMMIT(); CP_WAIT(1); }
        else            { CP_WAIT(0); }
        __syncthreads();
        const int st = kc & 1;

        uint32_t bh[4][4], bl[4][4];
        const uint32_t bbase_h = smem_u32(sBh[st]);
        const uint32_t bbase_l = smem_u32(sBl[st]);
        #pragma unroll
        for (int j = 0; j < 4; j++) {
            const uint32_t off = (uint32_t)((wn * 32 + j * 8 + b_r) * ASTR + b_c) * 2;
            ldm4(bh[j], bbase_h + off);
            ldm4(bl[j], bbase_l + off);
        }

        const uint32_t abase_h = smem_u32(sAh[st]);
        const uint32_t abase_l = smem_u32(sAl[st]);
        #pragma unroll
        for (int mi = 0; mi < 4; mi++) {
            uint32_t ah[2][4], al[2][4];
            #pragma unroll
            for (int kk = 0; kk < 2; kk++) {
                const uint32_t off =
                    (uint32_t)((wm * 64 + mi * 16 + a_r) * ASTR + kk * 16 + a_c) * 2;
                ldm4(ah[kk], abase_h + off);
                ldm4(al[kk], abase_l + off);
            }
            #pragma unroll
            for (int j = 0; j < 4; j++) {
                mma16816(c[mi][j], ah[0], bh[j][0], bh[j][1]);
                mma16816(c[mi][j], ah[1], bh[j][2], bh[j][3]);
                mma16816(c[mi][j], ah[0], bl[j][0], bl[j][1]);
                mma16816(c[mi][j], ah[1], bl[j][2], bl[j][3]);
                mma16816(c[mi][j], al[0], bh[j][0], bh[j][1]);
                mma16816(c[mi][j], al[1], bh[j][2], bh[j][3]);
            }
        }
        __syncthreads();
    }

    // ---- epilogue ----
    const int which = n0 >> 8;            // 0=Q 1=K 2=V
    const int r4 = lane >> 2, t4 = lane & 3;
    #pragma unroll
    for (int j = 0; j < 4; j++) {
        const int n3 = n0 + wn * 32 + j * 8 + t4 * 2;
        const int cc = n3 & 255, h = cc >> 5, d = cc & 31;
        const float b0 = __ldg(&bias[n3]), b1 = __ldg(&bias[n3 + 1]);
        #pragma unroll
        for (int mi = 0; mi < 4; mi++) {
            #pragma unroll
            for (int half = 0; half < 2; half++) {
                const int m = m0 + wm * 64 + mi * 16 + r4 + half * 8;
                const int bb = m >> 11, n = m & 2047;
                float v0 = c[mi][j][2 * half + 0] + b0;
                float v1 = c[mi][j][2 * half + 1] + b1;
                const size_t idx = ((size_t)(bb * NHEAD + h) * SEQ + n) * HD + d;
                if (which == 0) {
                    v0 *= QK_SCALE_L2E; v1 *= QK_SCALE_L2E;
                    uint32_t hw, lw;
                    split_pack_f16(v0, v1, hw, lw);
                    *reinterpret_cast<uint32_t*>(&g_qh[idx]) = hw;
                    *reinterpret_cast<uint32_t*>(&g_ql[idx]) = lw;
                } else if (which == 1) {
                    uint32_t hw, lw;
                    split_pack_f16(v0, v1, hw, lw);
                    *reinterpret_cast<uint32_t*>(&g_kh[idx]) = hw;
                    *reinterpret_cast<uint32_t*>(&g_kl[idx]) = lw;
                } else {
                    *reinterpret_cast<uint32_t*>(&g_v16[idx]) = pack_f16(v0, v1);
                }
            }
        }
    }
}

// ---------------------------------------------------------------------------
// V transpose (f16): g_v16[bh][n][d] -> g_vth[bh][d][n]
// grid (16 n-blocks of 128, 32 bh), 256 threads
// ---------------------------------------------------------------------------
__global__ __launch_bounds__(256) void vtrans() {
    __shared__ uint32_t Vs[128][17];     // [n][d-pair]
    const int tid = threadIdx.x;
    const int bh = blockIdx.y;
    const int n0 = blockIdx.x * 128;
    const uint32_t* gv = reinterpret_cast<const uint32_t*>(g_v16) +
                         ((size_t)bh * SEQ + n0) * (HD / 2);

    const int r = tid >> 1, c0 = (tid & 1) * 8;
    uint4 a = *reinterpret_cast<const uint4*>(gv + (size_t)r * 16 + c0);
    uint4 b = *reinterpret_cast<const uint4*>(gv + (size_t)r * 16 + c0 + 4);
    Vs[r][c0 + 0] = a.x; Vs[r][c0 + 1] = a.y; Vs[r][c0 + 2] = a.z; Vs[r][c0 + 3] = a.w;
    Vs[r][c0 + 4] = b.x; Vs[r][c0 + 5] = b.y; Vs[r][c0 + 6] = b.z; Vs[r][c0 + 7] = b.w;
    __syncthreads();

    const int dp = tid & 15, nblk = tid >> 4;
    uint32_t lo[4], hi[4];
    #pragma unroll
    for (int j = 0; j < 4; j++) {
        uint32_t w0 = Vs[nblk * 8 + 2 * j][dp];
        uint32_t w1 = Vs[nblk * 8 + 2 * j + 1][dp];
        lo[j] = __byte_perm(w0, w1, 0x5410);   // d = 2*dp
        hi[j] = __byte_perm(w0, w1, 0x7632);   // d = 2*dp+1
    }
    uint32_t* gt = reinterpret_cast<uint32_t*>(g_vth);
    const size_t o_lo = (((size_t)bh * HD + 2 * dp) * SEQ + n0 + nblk * 8) >> 1;
    const size_t o_hi = (((size_t)bh * HD + 2 * dp + 1) * SEQ + n0 + nblk * 8) >> 1;
    *reinterpret_cast<uint4*>(gt + o_lo) = make_uint4(lo[0], lo[1], lo[2], lo[3]);
    *reinterpret_cast<uint4*>(gt + o_hi) = make_uint4(hi[0], hi[1], hi[2], hi[3]);
}

// ---------------------------------------------------------------------------
// Flash attention via mma.sync f16: QK 3-term, PV single-term, exp2 softmax.
// CTA = 128 thr (4 warps), q-tile 64 rows, k-tile 64, cp.async x2.
// ---------------------------------------------------------------------------
#define KSTR 40
#define VSTR 72

__global__ __launch_bounds__(128) void flash_attn(float* __restrict__ out) {
    __shared__ __half sKh[2][64 * KSTR];
    __shared__ __half sKl[2][64 * KSTR];
    __shared__ __half sVh[2][32 * VSTR];

    const int tid  = threadIdx.x;
    const int lane = tid & 31;
    const int wid  = tid >> 5;
    const int qt   = 31 - blockIdx.x;     // heavy tiles first
    const int bh   = blockIdx.y;
    const int b    = bh >> 3, h = bh & 7;

    const uint32_t aKh[2] = { smem_u32(sKh[0]), smem_u32(sKh[1]) };
    const uint32_t aKl[2] = { smem_u32(sKl[0]), smem_u32(sKl[1]) };
    const uint32_t aVh[2] = { smem_u32(sVh[0]), smem_u32(sVh[1]) };

    uint32_t qh[2][4], ql[2][4];
    {
        const size_t qbase = ((size_t)bh * SEQ + qt * 64 + wid * 16) * HD;
        const uint32_t* qhp = reinterpret_cast<const uint32_t*>(g_qh) + qbase / 2;
        const uint32_t* qlp = reinterpret_cast<const uint32_t*>(g_ql) + qbase / 2;
        const int r = lane >> 2, t4 = lane & 3;
        #pragma unroll
        for (int kk = 0; kk < 2; kk++) {
            qh[kk][0] = qhp[r * 16 + kk * 8 + t4];
            qh[kk][1] = qhp[(r + 8) * 16 + kk * 8 + t4];
            qh[kk][2] = qhp[r * 16 + kk * 8 + 4 + t4];
            qh[kk][3] = qhp[(r + 8) * 16 + kk * 8 + 4 + t4];
            ql[kk][0] = qlp[r * 16 + kk * 8 + t4];
            ql[kk][1] = qlp[(r + 8) * 16 + kk * 8 + t4];
            ql[kk][2] = qlp[r * 16 + kk * 8 + 4 + t4];
            ql[kk][3] = qlp[(r + 8) * 16 + kk * 8 + 4 + t4];
        }
    }

    const int nkt = (qt < 16) ? 16 : (qt + 1);
    float o[4][4] = {};
    float l0 = 0.f, l1 = 0.f;

    auto load_tiles = [&](int st, int kt) {
        {
            const int row = tid >> 1, seg = (tid & 1) << 4;
            const size_t gk = ((size_t)bh * SEQ + kt * 64 + row) * HD + seg;
            const uint32_t sk = (uint32_t)(row * KSTR + seg) * 2;
            cpa16(aKh[st] + sk,      g_kh + gk);
            cpa16(aKh[st] + sk + 16, g_kh + gk + 8);
            cpa16(aKl[st] + sk,      g_kl + gk);
            cpa16(aKl[st] + sk + 16, g_kl + gk + 8);
        }
        {
            const int dr = tid >> 2, seg = (tid & 3) << 4;
            const size_t gv = ((size_t)bh * HD + dr) * SEQ + kt * 64 + seg;
            const uint32_t sv = (uint32_t)(dr * VSTR + seg) * 2;
            cpa16(aVh[st] + sv,      g_vth + gv);
            cpa16(aVh[st] + sv + 16, g_vth + gv + 8);
        }
    };

    load_tiles(0, 0);
    CP_COMMIT();

    const int r4 = lane >> 2, t4 = lane & 3;
    const int lm_row = lane & 7, lm_cb = lane >> 3;

    for (int kt = 0; kt < nkt; kt++) {
        if (kt + 1 < nkt) { load_tiles((kt + 1) & 1, kt + 1); CP_COMMIT(); CP_WAIT(1); }
        else              { CP_WAIT(0); }
        __syncthreads();

        const int st = kt & 1;

        // ---- S = Q K^T (3-term f16) ----
        float s[8][4];
        #pragma unroll
        for (int j = 0; j < 8; j++) { s[j][0] = s[j][1] = s[j][2] = s[j][3] = 0.f; }

        #pragma unroll
        for (int j = 0; j < 8; j++) {
            uint32_t kh[4], kl[4];
            const uint32_t off = (uint32_t)((j * 8 + lm_row) * KSTR + lm_cb * 8) * 2;
            ldm4(kh, aKh[st] + off);
            ldm4(kl, aKl[st] + off);
            mma16816(s[j], qh[0], kh[0], kh[1]);
            mma16816(s[j], qh[1], kh[2], kh[3]);
            mma16816(s[j], qh[0], kl[0], kl[1]);
            mma16816(s[j], qh[1], kl[2], kl[3]);
            mma16816(s[j], ql[0], kh[0], kh[1]);
            mma16816(s[j], ql[1], kh[2], kh[3]);
        }

        // ---- p = 2^s (log2e folded into Q), diagonal mask, row sums ----
        const bool diag = (qt >= 16) && (kt == qt);
        #pragma unroll
        for (int j = 0; j < 8; j++) {
            float p0 = ex2(s[j][0]), p1 = ex2(s[j][1]);
            float p2 = ex2(s[j][2]), p3 = ex2(s[j][3]);
            if (diag) {
                const int key0 = kt * 64 + j * 8 + t4 * 2;
                const int r0 = qt * 64 + wid * 16 + r4;
                if (key0     > r0)     p0 = 0.f;
                if (key0 + 1 > r0)     p1 = 0.f;
                if (key0     > r0 + 8) p2 = 0.f;
                if (key0 + 1 > r0 + 8) p3 = 0.f;
            }
            l0 += p0 + p1; l1 += p2 + p3;
            s[j][0] = p0; s[j][1] = p1; s[j][2] = p2; s[j][3] = p3;
        }

        // ---- P -> f16 A frags (single term, no residual) ----
        uint32_t ah[4][4];
        #pragma unroll
        for (int kk = 0; kk < 4; kk++) {
            const int j0 = 2 * kk, j1 = 2 * kk + 1;
            ah[kk][0] = pack_f16(s[j0][0], s[j0][1]);
            ah[kk][1] = pack_f16(s[j0][2], s[j0][3]);
            ah[kk][2] = pack_f16(s[j1][0], s[j1][1]);
            ah[kk][3] = pack_f16(s[j1][2], s[j1][3]);
        }

        // ---- O += P V (single term) ----
        #pragma unroll
        for (int nd = 0; nd < 4; nd++) {
            uint32_t vh[8];
            const uint32_t ro = (uint32_t)((nd * 8 + lm_row) * VSTR) * 2;
            ldm4(vh,     aVh[st] + ro + (uint32_t)(lm_cb * 8) * 2);
            ldm4(vh + 4, aVh[st] + ro + (uint32_t)(32 + lm_cb * 8) * 2);
            #pragma unroll
            for (int kk = 0; kk < 4; kk++)
                mma16816(o[nd], ah[kk], vh[2 * kk], vh[2 * kk + 1]);
        }
        __syncthreads();
    }

    l0 += __shfl_xor_sync(0xffffffffu, l0, 1);
    l0 += __shfl_xor_sync(0xffffffffu, l0, 2);
    l1 += __shfl_xor_sync(0xffffffffu, l1, 1);
    l1 += __shfl_xor_sync(0xffffffffu, l1, 2);
    const float inv0 = 1.f / l0, inv1 = 1.f / l1;

    const int row0 = qt * 64 + wid * 16 + r4;
    #pragma unroll
    for (int nd = 0; nd < 4; nd++) {
        const int d0 = nd * 8 + t4 * 2;
        const size_t o0 = ((size_t)(b * SEQ + row0)) * DIM + h * HD + d0;
        const size_t o1 = ((size_t)(b * SEQ + row0 + 8)) * DIM + h * HD + d0;
        *reinterpret_cast<float2*>(&out[o0]) = make_float2(o[nd][0] * inv0, o[nd][1] * inv0);
        *reinterpret_cast<float2*>(&out[o1]) = make_float2(o[nd][2] * inv1, o[nd][3] * inv1);
    }
}

extern "C" void kernel_launch(void* const* d_in, const int* in_sizes, int n_in,
                              void* d_out, int out_size) {
    const float* x    = (const float*)d_in[0];
    const float* W    = (const float*)d_in[1];
    const float* bias = (const float*)d_in[2];
    float* out = (float*)d_out;

    static int init_done = 0;
    if (!init_done) {
        cudaFuncSetAttribute(qkv_mma,
                             cudaFuncAttributeMaxDynamicSharedMemorySize,
                             8 * TILEB * (int)sizeof(__half));
        init_done = 1;
    }

    xsplit<<<2048, 256>>>(x);
    wsplit<<<dim3(12, 4), 256>>>(W);
    qkv_mma<<<dim3(64, 6), 256, 8 * TILEB * sizeof(__half)>>>(bias);

    dim3 vt_grid(16, 32);
    vtrans<<<vt_grid, 256>>>();

    dim3 attn_grid(32, 32);
    flash_attn<<<attn_grid, 128>>>(out);
}